// round 3
// baseline (speedup 1.0000x reference)
#include <cuda_runtime.h>

#define B_DIM 2
#define E_DIM 1024
#define C_DIM 128
#define R_REL 32

// 8 MB scratch for the Gram matrices G[b,s,o].
__device__ float g_G[(size_t)B_DIM * E_DIM * E_DIM];

// ---------------------------------------------------------------------------
// Kernel 1: G[b] = X[b] @ X[b]^T  (1024x1024, K=128), SYMMETRIC.
// Only upper-triangular 128x128 tiles are computed (36 per batch);
// off-diagonal tiles are written twice (normal + transposed).
// 256 threads, 8x8 register tile, split 4+4 groups, k-major SMEM.
// ---------------------------------------------------------------------------
__global__ __launch_bounds__(256) void gram_kernel(const float* __restrict__ x) {
    const int b    = blockIdx.z;
    const float* X = x + (size_t)b * E_DIM * C_DIM;
    float* Gb      = g_G + (size_t)b * E_DIM * E_DIM;

    // Map linear tile index 0..35 -> (bi, bj) with bi <= bj (8x8 tile grid).
    int idx = blockIdx.x;
    int bi = 0;
    while (idx >= 8 - bi) { idx -= 8 - bi; bi++; }
    const int bj = bi + idx;

    const int row0 = bi * 128;
    const int col0 = bj * 128;
    const int tid  = threadIdx.x;
    const int tx   = tid & 15;
    const int ty   = tid >> 4;

    __shared__ float As[16][132];   // k-major: As[k][row]
    __shared__ float Bs[16][132];   // k-major: Bs[k][col]

    float acc[8][8];
    #pragma unroll
    for (int i = 0; i < 8; i++)
        #pragma unroll
        for (int j = 0; j < 8; j++) acc[i][j] = 0.f;

    for (int kk = 0; kk < C_DIM; kk += 16) {
        #pragma unroll
        for (int i = 0; i < 2; i++) {
            int flat = tid + i * 256;        // 0..511
            int rr   = flat >> 2;            // 0..127
            int kq   = (flat & 3) * 4;       // 0,4,8,12
            float4 av = *(const float4*)&X[(size_t)(row0 + rr) * C_DIM + kk + kq];
            float4 bv = *(const float4*)&X[(size_t)(col0 + rr) * C_DIM + kk + kq];
            As[kq + 0][rr] = av.x; As[kq + 1][rr] = av.y;
            As[kq + 2][rr] = av.z; As[kq + 3][rr] = av.w;
            Bs[kq + 0][rr] = bv.x; Bs[kq + 1][rr] = bv.y;
            Bs[kq + 2][rr] = bv.z; Bs[kq + 3][rr] = bv.w;
        }
        __syncthreads();

        #pragma unroll
        for (int k = 0; k < 16; k++) {
            float4 a0 = *(const float4*)&As[k][ty * 4];
            float4 a1 = *(const float4*)&As[k][64 + ty * 4];
            float4 b0 = *(const float4*)&Bs[k][tx * 4];
            float4 b1 = *(const float4*)&Bs[k][64 + tx * 4];
            float a[8]  = {a0.x, a0.y, a0.z, a0.w, a1.x, a1.y, a1.z, a1.w};
            float bb[8] = {b0.x, b0.y, b0.z, b0.w, b1.x, b1.y, b1.z, b1.w};
            #pragma unroll
            for (int i = 0; i < 8; i++)
                #pragma unroll
                for (int j = 0; j < 8; j++)
                    acc[i][j] = fmaf(a[i], bb[j], acc[i][j]);
        }
        __syncthreads();
    }

    // Normal tile store (coalesced float4 rows).
    #pragma unroll
    for (int ig = 0; ig < 2; ig++) {
        #pragma unroll
        for (int i = 0; i < 4; i++) {
            int row = row0 + ig * 64 + ty * 4 + i;
            float* dst = &Gb[(size_t)row * E_DIM + col0];
            *(float4*)&dst[tx * 4] =
                make_float4(acc[ig*4+i][0], acc[ig*4+i][1], acc[ig*4+i][2], acc[ig*4+i][3]);
            *(float4*)&dst[64 + tx * 4] =
                make_float4(acc[ig*4+i][4], acc[ig*4+i][5], acc[ig*4+i][6], acc[ig*4+i][7]);
        }
    }

    // Transposed tile store for off-diagonal tiles: G[col][row] = acc^T.
    // float4 gathered along the row (i) direction -> 32B sectors fully used.
    if (bi != bj) {
        #pragma unroll
        for (int jg = 0; jg < 2; jg++) {
            #pragma unroll
            for (int j = 0; j < 4; j++) {
                int col = col0 + jg * 64 + tx * 4 + j;
                float* dst = &Gb[(size_t)col * E_DIM + row0];
                *(float4*)&dst[ty * 4] =
                    make_float4(acc[0][jg*4+j], acc[1][jg*4+j], acc[2][jg*4+j], acc[3][jg*4+j]);
                *(float4*)&dst[64 + ty * 4] =
                    make_float4(acc[4][jg*4+j], acc[5][jg*4+j], acc[6][jg*4+j], acc[7][jg*4+j]);
            }
        }
    }
}

// ---------------------------------------------------------------------------
// Kernel 2: out[b,s,r,o] = G[b,s,o] * R[r,s,o]
// One block per (s, 8-r chunk). All 8 R rows preloaded (explicit MLP=8),
// G rows in registers (L2-resident reads), outputs streamed with __stcs.
// ---------------------------------------------------------------------------
#define RCHUNK 8

__global__ __launch_bounds__(256) void scale_kernel(const float4* __restrict__ Rrel,
                                                    float4* __restrict__ out) {
    const int E4  = E_DIM / 4;                 // 256 float4 per row
    const int bid = blockIdx.x;
    const int s   = bid >> 2;                  // / (R_REL/RCHUNK)
    const int rc  = (bid & 3) * RCHUNK;
    const int t   = threadIdx.x;               // 0..255

    const float4* G = (const float4*)g_G;
    float4 g0 = __ldg(&G[(size_t)s * E4 + t]);
    float4 g1 = __ldg(&G[((size_t)E_DIM + s) * E4 + t]);

    // Batch all 8 streaming R loads up-front for maximum MLP.
    float4 rv[RCHUNK];
    #pragma unroll
    for (int rr = 0; rr < RCHUNK; rr++)
        rv[rr] = __ldcs(&Rrel[((size_t)(rc + rr) * E_DIM + s) * E4 + t]);

    #pragma unroll
    for (int rr = 0; rr < RCHUNK; rr++) {
        const int r = rc + rr;
        float4 o0, o1;
        o0.x = g0.x * rv[rr].x;  o0.y = g0.y * rv[rr].y;
        o0.z = g0.z * rv[rr].z;  o0.w = g0.w * rv[rr].w;
        o1.x = g1.x * rv[rr].x;  o1.y = g1.y * rv[rr].y;
        o1.z = g1.z * rv[rr].z;  o1.w = g1.w * rv[rr].w;

        size_t base0 = (((size_t)s) * R_REL + r) * (size_t)E4 + t;
        size_t base1 = (((size_t)E_DIM + s) * R_REL + r) * (size_t)E4 + t;
        __stcs(&out[base0], o0);
        __stcs(&out[base1], o1);
    }
}

extern "C" void kernel_launch(void* const* d_in, const int* in_sizes, int n_in,
                              void* d_out, int out_size) {
    const float* x  = (const float*)d_in[0];   // (B, E, C) fp32
    const float* Rr = (const float*)d_in[1];   // (R_REL, E, E) fp32
    float* out      = (float*)d_out;           // (B, E, R_REL, E) fp32

    dim3 ggrid(36, 1, B_DIM);                  // upper-triangular tiles x batch
    gram_kernel<<<ggrid, 256>>>(x);

    scale_kernel<<<E_DIM * (R_REL / RCHUNK), 256>>>((const float4*)Rr, (float4*)out);

    (void)in_sizes; (void)n_in; (void)out_size;
}